// round 3
// baseline (speedup 1.0000x reference)
#include <cuda_runtime.h>

#define THREADS 384
#define L 2500
#define HALF 1251          // bins 0..1250
#define PATCHES 50
#define TWN 500            // master twiddle table: W_2500^j, j=0..499
#define GROUP 192          // threads per batch in the search phase

__device__ __forceinline__ float2 cmul(float2 a, float2 b) {
    return make_float2(a.x * b.x - a.y * b.y, a.x * b.y + a.y * b.x);
}

// radix-5 constants (w = e^{-2pi i/5})
#define CR1 ( 0.30901699437494742f)
#define CR2 (-0.80901699437494742f)
#define SI1 ( 0.95105651629515357f)
#define SI2 ( 0.58778525229247314f)

// Stockham DIF radix-5 stage, natural-order autosort.
template <int NN, int SS>
__device__ __forceinline__ void stage5(const float2* __restrict__ X, float2* __restrict__ Y,
                                       const float2* __restrict__ tw, int tid) {
    constexpr int M = NN / 5;
    constexpr int STRIDE = 2500 / NN;
    constexpr int WORK = M * SS;   // always 500
    for (int w = tid; w < WORK; w += THREADS) {
        const int q = w % SS;
        const int p = w / SS;
        float2 a0 = X[q + SS * p];
        float2 a1 = X[q + SS * (p + M)];
        float2 a2 = X[q + SS * (p + 2 * M)];
        float2 a3 = X[q + SS * (p + 3 * M)];
        float2 a4 = X[q + SS * (p + 4 * M)];
        float2 t1 = make_float2(a1.x + a4.x, a1.y + a4.y);
        float2 t2 = make_float2(a2.x + a3.x, a2.y + a3.y);
        float2 t3 = make_float2(a1.x - a4.x, a1.y - a4.y);
        float2 t4 = make_float2(a2.x - a3.x, a2.y - a3.y);
        float2 c0 = make_float2(a0.x + t1.x + t2.x, a0.y + t1.y + t2.y);
        float2 m1 = make_float2(a0.x + CR1 * t1.x + CR2 * t2.x, a0.y + CR1 * t1.y + CR2 * t2.y);
        float2 m2 = make_float2(a0.x + CR2 * t1.x + CR1 * t2.x, a0.y + CR2 * t1.y + CR1 * t2.y);
        float2 s1 = make_float2(SI1 * t3.x + SI2 * t4.x, SI1 * t3.y + SI2 * t4.y);
        float2 s2 = make_float2(SI2 * t3.x - SI1 * t4.x, SI2 * t3.y - SI1 * t4.y);
        float2 c1 = make_float2(m1.x + s1.y, m1.y - s1.x);
        float2 c4 = make_float2(m1.x - s1.y, m1.y + s1.x);
        float2 c2 = make_float2(m2.x + s2.y, m2.y - s2.x);
        float2 c3 = make_float2(m2.x - s2.y, m2.y + s2.x);
        float2 w1 = tw[p * STRIDE];
        float2 w2 = cmul(w1, w1);
        float2 w3 = cmul(w2, w1);
        float2 w4 = cmul(w2, w2);
        const int ob = q + SS * 5 * p;
        Y[ob]          = c0;
        Y[ob + SS]     = cmul(c1, w1);
        Y[ob + 2 * SS] = cmul(c2, w2);
        Y[ob + 3 * SS] = cmul(c3, w3);
        Y[ob + 4 * SS] = cmul(c4, w4);
    }
}

// Insert (v, i) into a sorted (desc value, asc index on ties) register triple.
__device__ __forceinline__ void ins3(float v, int i,
                                     float& v0, int& i0, float& v1, int& i1,
                                     float& v2, int& i2) {
    if (v > v0 || (v == v0 && i < i0)) {
        v2 = v1; i2 = i1; v1 = v0; i1 = i0; v0 = v; i0 = i;
    } else if (v > v1 || (v == v1 && i < i1)) {
        v2 = v1; i2 = i1; v1 = v; i1 = i;
    } else if (v > v2 || (v == v2 && i < i2)) {
        v2 = v; i2 = i;
    }
}

__global__ __launch_bounds__(THREADS)
void TimeSeriesWeighting_kernel(const float* __restrict__ x,
                                const float* __restrict__ wscal,
                                float* __restrict__ out) {
    __shared__ float2 bufA[L];
    __shared__ float2 bufB[L];
    __shared__ float2 tw[TWN];
    __shared__ float wv[THREADS / 32][3];
    __shared__ int   wi[THREADS / 32][3];
    __shared__ int   top_idx[2][3];

    const int tid = threadIdx.x;
    const long long b0 = 2LL * blockIdx.x;

    // Pack two batches' head-0 rows: z = x_a + i*x_b (rows 30000 floats apart, 16B-aligned)
    const float4* sa = reinterpret_cast<const float4*>(x + b0 * 30000);
    const float4* sb = reinterpret_cast<const float4*>(x + (b0 + 1) * 30000);
    for (int i = tid; i < 625; i += THREADS) {
        float4 va = sa[i], vb = sb[i];
        int j = i * 4;
        bufA[j]     = make_float2(va.x, vb.x);
        bufA[j + 1] = make_float2(va.y, vb.y);
        bufA[j + 2] = make_float2(va.z, vb.z);
        bufA[j + 3] = make_float2(va.w, vb.w);
    }
    // Master twiddle table via fast MUFU sincos (ranking-safe: ~1e-6 rel error on powers)
    for (int j = tid; j < TWN; j += THREADS) {
        float sn, cs;
        __sincosf(-6.283185307179586f * (float)j / 2500.0f, &sn, &cs);
        tw[j] = make_float2(cs, sn);
    }
    __syncthreads();

    // 2500 = 5*5*5*5*4 mixed-radix Stockham (autosort -> natural order)
    stage5<2500, 1>(bufA, bufB, tw, tid);  __syncthreads();
    stage5<500, 5>(bufB, bufA, tw, tid);   __syncthreads();
    stage5<100, 25>(bufA, bufB, tw, tid);  __syncthreads();
    stage5<20, 125>(bufB, bufA, tw, tid);  __syncthreads();
    // final radix-4 stage: NN=4, SS=625, twiddle = 1
    for (int q = tid; q < 625; q += THREADS) {
        float2 a0 = bufA[q], a1 = bufA[q + 625], a2 = bufA[q + 1250], a3 = bufA[q + 1875];
        float2 e0 = make_float2(a0.x + a2.x, a0.y + a2.y);
        float2 e1 = make_float2(a0.x - a2.x, a0.y - a2.y);
        float2 o0 = make_float2(a1.x + a3.x, a1.y + a3.y);
        float2 o1 = make_float2(a1.x - a3.x, a1.y - a3.y);
        bufB[q]        = make_float2(e0.x + o0.x, e0.y + o0.y);
        bufB[q + 625]  = make_float2(e1.x + o1.y, e1.y - o1.x);
        bufB[q + 1250] = make_float2(e0.x - o0.x, e0.y - o0.y);
        bufB[q + 1875] = make_float2(e1.x - o1.y, e1.y + o1.x);
    }
    __syncthreads();

    // Fused power-spectrum + top-3 search (single pass, register triples).
    // Packed-split: pw_a[k] ∝ |Z[k]+conj(Z[N-k])|^2, pw_b[k] ∝ |Z[k]-conj(Z[N-k])|^2
    // Group 0 = threads [0,192) -> batch a; group 1 = [192,384) -> batch b.
    const int g = (tid >= GROUP);
    const int lt = tid - g * GROUP;

    float v0 = -1.0f, v1 = -1.0f, v2 = -1.0f;
    int   i0 = 0x7fffffff, i1 = 0x7fffffff, i2 = 0x7fffffff;
    for (int k = lt; k < HALF; k += GROUP) {
        float2 zk = bufB[k];
        float2 zm = bufB[k == 0 ? 0 : (L - k)];
        float vx, vy;
        if (g == 0) { vx = zk.x + zm.x; vy = zk.y - zm.y; }
        else        { vx = zk.x - zm.x; vy = zk.y + zm.y; }
        float v = vx * vx + vy * vy;
        ins3(v, k, v0, i0, v1, i1, v2, i2);
    }
    // warp-level merge of sorted triples
    #pragma unroll
    for (int off = 16; off > 0; off >>= 1) {
        float ov0 = __shfl_xor_sync(0xffffffffu, v0, off);
        int   oi0 = __shfl_xor_sync(0xffffffffu, i0, off);
        float ov1 = __shfl_xor_sync(0xffffffffu, v1, off);
        int   oi1 = __shfl_xor_sync(0xffffffffu, i1, off);
        float ov2 = __shfl_xor_sync(0xffffffffu, v2, off);
        int   oi2 = __shfl_xor_sync(0xffffffffu, i2, off);
        ins3(ov0, oi0, v0, i0, v1, i1, v2, i2);
        ins3(ov1, oi1, v0, i0, v1, i1, v2, i2);
        ins3(ov2, oi2, v0, i0, v1, i1, v2, i2);
    }
    const int wid = tid >> 5;           // 0..11; warps 0-5 = g0, 6-11 = g1
    if ((tid & 31) == 0) {
        wv[wid][0] = v0; wi[wid][0] = i0;
        wv[wid][1] = v1; wi[wid][1] = i1;
        wv[wid][2] = v2; wi[wid][2] = i2;
    }
    __syncthreads();
    if (lt == 0) {
        const int base = g * 6;
        float f0 = wv[base][0], f1 = wv[base][1], f2 = wv[base][2];
        int   j0 = wi[base][0], j1 = wi[base][1], j2 = wi[base][2];
        #pragma unroll
        for (int wq = 1; wq < 6; wq++) {
            ins3(wv[base + wq][0], wi[base + wq][0], f0, j0, f1, j1, f2, j2);
            ins3(wv[base + wq][1], wi[base + wq][1], f0, j0, f1, j1, f2, j2);
            ins3(wv[base + wq][2], wi[base + wq][2], f0, j0, f1, j1, f2, j2);
        }
        top_idx[g][0] = j0; top_idx[g][1] = j1; top_idx[g][2] = j2;
    }
    __syncthreads();

    // Full-spectrum ranks {0, 2} from half-spectrum top-3 with pair multiplicity:
    // DC (0) and Nyquist (1250) appear once; other bins twice (k, 2500-k).
    const int h0 = top_idx[g][0], h1 = top_idx[g][1], h2 = top_idx[g][2];
    const bool h0_pair = (h0 != 0 && h0 != 1250);
    const bool h1_pair = (h1 != 0 && h1 != 1250);
    const int ka = h0;
    const int kb = (h0_pair || h1_pair) ? h1 : h2;

    if (lt < PATCHES) {
        const float wgt = 12.0f * wscal[0];  // N * weights
        const int start = lt * 50;
        int cnt = 0;
        if (ka != 0) {
            int p = L / ka;
            int fm = ((start + p - 1) / p) * p;
            cnt += (fm < start + 50);
        }
        if (kb != 0) {
            int p = L / kb;
            int fm = ((start + p - 1) / p) * p;
            cnt += (fm < start + 50);
        }
        out[(b0 + g) * PATCHES + lt] = wgt * (float)cnt;
    }
}

extern "C" void kernel_launch(void* const* d_in, const int* in_sizes, int n_in,
                              void* d_out, int out_size) {
    const float* x = (const float*)d_in[0];
    const float* w = (const float*)d_in[1];
    int xs = in_sizes[0];
    if (n_in >= 2 && in_sizes[0] < in_sizes[1]) {  // order-robust: scalar vs big tensor
        x = (const float*)d_in[1];
        w = (const float*)d_in[0];
        xs = in_sizes[1];
    }
    const int B = xs / (12 * L);   // 1024
    TimeSeriesWeighting_kernel<<<B / 2, THREADS>>>(x, w, (float*)d_out);
}

// round 4
// speedup vs baseline: 1.1100x; 1.1100x over previous
#include <cuda_runtime.h>

#define THREADS 256
#define L 2500
#define NF 1250            // complex FFT length (even/odd split of real 2500)
#define HALF 1251          // output bins 0..1250
#define PATCHES 50
#define TWN 626            // W_2500^j, j = 0..625

__device__ __forceinline__ float2 cmul(float2 a, float2 b) {
    return make_float2(a.x * b.x - a.y * b.y, a.x * b.y + a.y * b.x);
}

// radix-5 constants (w = e^{-2pi i/5})
#define CR1 ( 0.30901699437494742f)
#define CR2 (-0.80901699437494742f)
#define SI1 ( 0.95105651629515357f)
#define SI2 ( 0.58778525229247314f)

// Stockham DIF radix-5 stage for the 1250-pt FFT, natural-order autosort.
// WORK = (NN/5)*SS = 250 for every stage -> one item per thread, no loop.
// Twiddle: W_NN^p = W_2500^(2p*(1250/NN)), max index 498 < TWN.
template <int NN, int SS>
__device__ __forceinline__ void stage5(const float2* __restrict__ X, float2* __restrict__ Y,
                                       const float2* __restrict__ tw, int tid) {
    constexpr int M = NN / 5;            // sub-transform count
    constexpr int STRIDE = 2 * (NF / NN);
    if (tid < M * SS) {
        const int q = tid % SS;
        const int p = tid / SS;
        float2 a0 = X[q + SS * p];
        float2 a1 = X[q + SS * (p + M)];
        float2 a2 = X[q + SS * (p + 2 * M)];
        float2 a3 = X[q + SS * (p + 3 * M)];
        float2 a4 = X[q + SS * (p + 4 * M)];
        float2 t1 = make_float2(a1.x + a4.x, a1.y + a4.y);
        float2 t2 = make_float2(a2.x + a3.x, a2.y + a3.y);
        float2 t3 = make_float2(a1.x - a4.x, a1.y - a4.y);
        float2 t4 = make_float2(a2.x - a3.x, a2.y - a3.y);
        float2 c0 = make_float2(a0.x + t1.x + t2.x, a0.y + t1.y + t2.y);
        float2 m1 = make_float2(a0.x + CR1 * t1.x + CR2 * t2.x, a0.y + CR1 * t1.y + CR2 * t2.y);
        float2 m2 = make_float2(a0.x + CR2 * t1.x + CR1 * t2.x, a0.y + CR2 * t1.y + CR1 * t2.y);
        float2 s1 = make_float2(SI1 * t3.x + SI2 * t4.x, SI1 * t3.y + SI2 * t4.y);
        float2 s2 = make_float2(SI2 * t3.x - SI1 * t4.x, SI2 * t3.y - SI1 * t4.y);
        float2 c1 = make_float2(m1.x + s1.y, m1.y - s1.x);
        float2 c4 = make_float2(m1.x - s1.y, m1.y + s1.x);
        float2 c2 = make_float2(m2.x + s2.y, m2.y - s2.x);
        float2 c3 = make_float2(m2.x - s2.y, m2.y + s2.x);
        float2 w1 = tw[p * STRIDE];
        float2 w2 = cmul(w1, w1);
        float2 w3 = cmul(w2, w1);
        float2 w4 = cmul(w2, w2);
        const int ob = q + SS * 5 * p;
        Y[ob]          = c0;
        Y[ob + SS]     = cmul(c1, w1);
        Y[ob + 2 * SS] = cmul(c2, w2);
        Y[ob + 3 * SS] = cmul(c3, w3);
        Y[ob + 4 * SS] = cmul(c4, w4);
    }
}

__global__ __launch_bounds__(THREADS)
void TimeSeriesWeighting_kernel(const float* __restrict__ x,
                                const float* __restrict__ wscal,
                                float* __restrict__ out) {
    __shared__ float2 bufA[NF];
    __shared__ float2 bufB[NF];
    __shared__ float2 tw[TWN];
    __shared__ float s_v[THREADS / 32];
    __shared__ int   s_i[THREADS / 32];
    __shared__ int   top_idx[3];

    const int tid = threadIdx.x;
    const int b = blockIdx.x;

    // Load head-0 row (2500 floats, 16B aligned), pack even/odd: z[m] = x[2m] + i*x[2m+1]
    const float4* src = reinterpret_cast<const float4*>(x + (long long)b * 30000);
    for (int i = tid; i < 625; i += THREADS) {
        float4 v = src[i];
        bufA[2 * i]     = make_float2(v.x, v.y);
        bufA[2 * i + 1] = make_float2(v.z, v.w);
    }
    // W_2500^j table, j = 0..625 (fast MUFU sincos; ranking-safe)
    for (int j = tid; j < TWN; j += THREADS) {
        float sn, cs;
        __sincosf(-6.283185307179586f * (float)j * (1.0f / 2500.0f), &sn, &cs);
        tw[j] = make_float2(cs, sn);
    }
    __syncthreads();

    // 1250 = 5*5*5*5*2 mixed-radix Stockham (autosort -> natural order)
    stage5<1250, 1>(bufA, bufB, tw, tid);  __syncthreads();
    stage5<250, 5>(bufB, bufA, tw, tid);   __syncthreads();
    stage5<50, 25>(bufA, bufB, tw, tid);   __syncthreads();
    stage5<10, 125>(bufB, bufA, tw, tid);  __syncthreads();
    // final radix-2 stage: SS = 625, twiddle = 1
    for (int q = tid; q < 625; q += THREADS) {
        float2 a0 = bufA[q], a1 = bufA[q + 625];
        bufB[q]       = make_float2(a0.x + a1.x, a0.y + a1.y);
        bufB[q + 625] = make_float2(a0.x - a1.x, a0.y - a1.y);
    }
    __syncthreads();

    // Real-FFT combine + power, bins k = 0..1250 (uniform x4 scale dropped):
    //   Se = Z[k] + conj(Z[1250-k]);  So = -i*(Z[k] - conj(Z[1250-k]))
    //   X[k] = Se + W_2500^k * So ;  pw[k] = |X[k]|^2
    float* pw = reinterpret_cast<float*>(bufA);   // 1251 floats (bufA is free now)
    for (int k = tid; k < HALF; k += THREADS) {
        const int km = (k == 1250) ? 0 : k;
        const int j  = (km == 0) ? 0 : (NF - km);
        float2 zk = bufB[km];
        float2 zj = bufB[j];
        float2 se = make_float2(zk.x + zj.x, zk.y - zj.y);
        float2 so = make_float2(zk.y + zj.y, -(zk.x - zj.x));   // -i*(zk - conj(zj))
        float2 w;
        if (k < 625) w = tw[k];
        else { float2 t = tw[k - 625]; w = make_float2(t.y, -t.x); }  // W^k = -i*W^(k-625)
        float2 ws = cmul(w, so);
        float vx = se.x + ws.x, vy = se.y + ws.y;
        pw[k] = vx * vx + vy * vy;
    }
    __syncthreads();

    // top-3 half-spectrum bins (value desc, tie -> smaller index), 3 exclusion passes
    for (int r = 0; r < 3; r++) {
        const int e0 = (r > 0) ? top_idx[0] : -1;
        const int e1 = (r > 1) ? top_idx[1] : -1;
        float bv = -1.0f;
        int bi = 0x7fffffff;
        for (int k = tid; k < HALF; k += THREADS) {
            if (k == e0 || k == e1) continue;
            float v = pw[k];
            if (v > bv || (v == bv && k < bi)) { bv = v; bi = k; }
        }
        #pragma unroll
        for (int off = 16; off > 0; off >>= 1) {
            float ov = __shfl_down_sync(0xffffffffu, bv, off);
            int   oi = __shfl_down_sync(0xffffffffu, bi, off);
            if (ov > bv || (ov == bv && oi < bi)) { bv = ov; bi = oi; }
        }
        if ((tid & 31) == 0) { s_v[tid >> 5] = bv; s_i[tid >> 5] = bi; }
        __syncthreads();
        if (tid == 0) {
            float fv = s_v[0]; int fi = s_i[0];
            #pragma unroll
            for (int wv = 1; wv < THREADS / 32; wv++) {
                if (s_v[wv] > fv || (s_v[wv] == fv && s_i[wv] < fi)) { fv = s_v[wv]; fi = s_i[wv]; }
            }
            top_idx[r] = fi;
        }
        __syncthreads();
    }

    // Full-spectrum ranks {0, 2} from half-spectrum top-3 with pair multiplicity:
    // DC (0) and Nyquist (1250) appear once; other bins twice (k, 2500-k).
    const int h0 = top_idx[0], h1 = top_idx[1], h2 = top_idx[2];
    const bool h0_pair = (h0 != 0 && h0 != 1250);
    const bool h1_pair = (h1 != 0 && h1 != 1250);
    const int ka = h0;
    const int kb = (h0_pair || h1_pair) ? h1 : h2;

    if (tid < PATCHES) {
        const float wgt = 12.0f * wscal[0];  // N * weights
        const int start = tid * 50;
        int cnt = 0;
        if (ka != 0) {
            int p = L / ka;
            int fm = ((start + p - 1) / p) * p;
            cnt += (fm < start + 50);
        }
        if (kb != 0) {
            int p = L / kb;
            int fm = ((start + p - 1) / p) * p;
            cnt += (fm < start + 50);
        }
        out[b * PATCHES + tid] = wgt * (float)cnt;
    }
}

extern "C" void kernel_launch(void* const* d_in, const int* in_sizes, int n_in,
                              void* d_out, int out_size) {
    const float* x = (const float*)d_in[0];
    const float* w = (const float*)d_in[1];
    int xs = in_sizes[0];
    if (n_in >= 2 && in_sizes[0] < in_sizes[1]) {  // order-robust: scalar vs big tensor
        x = (const float*)d_in[1];
        w = (const float*)d_in[0];
        xs = in_sizes[1];
    }
    const int B = xs / (12 * L);   // 1024
    TimeSeriesWeighting_kernel<<<B, THREADS>>>(x, w, (float*)d_out);
}